// round 9
// baseline (speedup 1.0000x reference)
#include <cuda_runtime.h>
#include <cuda_fp16.h>
#include <math_constants.h>
#include <cstdint>

// Problem constants (match reference)
#define D         128
#define N_SRC_MAX 50000
#define N_DST_MAX 50000
#define E_MAX     1600000
#define INV_SCALE 0.25f          // 1/sqrt(128/8) = 1/4

// ---------------- scratch (no allocations allowed) ----------------
__device__ __align__(128) float  g_Q[N_DST_MAX * D];
__device__ __align__(128) float  g_K[N_SRC_MAX * D];
__device__ __align__(128) __half g_Vh[N_SRC_MAX * D];
__device__ __align__(128) float  g_score[E_MAX];
__device__ __align__(128) float  g_m[N_DST_MAX];
__device__ __align__(128) int    g_count[N_DST_MAX];
__device__ __align__(128) int    g_start[N_DST_MAX + 1];
__device__ __align__(128) int    g_cursor[N_DST_MAX];
__device__ __align__(128) int    g_perm_src[E_MAX];
__device__ __align__(128) int    g_bsum[128];
__device__ int g_is64;

// ---------------- helpers ----------------
__device__ __forceinline__ int load_idx(const void* p, int i) {
    if (g_is64) return (int)((const long long*)p)[i];
    return ((const int*)p)[i];
}
__device__ __forceinline__ void fma2(unsigned long long& d,
                                     unsigned long long a, unsigned long long b) {
    asm("fma.rn.f32x2 %0, %1, %2, %0;" : "+l"(d) : "l"(a), "l"(b));
}
__device__ __forceinline__ unsigned long long pack2(float x) {
    unsigned long long r;
    asm("mov.b64 %0, {%1, %1};" : "=l"(r) : "f"(x));
    return r;
}

// ---------------- dtype detection ----------------
__global__ void detect_idx_kernel(const void* src_idx, const void* dst_idx,
                                  int n_src, int n_dst, int E) {
    if (threadIdx.x == 0) g_is64 = 1;
    __syncthreads();
    int i = threadIdx.x;
    int limit = (E / 2 < 64) ? E / 2 : 64;
    if (i < limit) {
        long long s = ((const long long*)src_idx)[i];
        long long d = ((const long long*)dst_idx)[i];
        bool ok = (s >= 0 && s < n_src && d >= 0 && d < n_dst);
        if (!ok) atomicExch(&g_is64, 0);
    }
}

__global__ void zero_counts_kernel(int n_dst) {
    int i = blockIdx.x * blockDim.x + threadIdx.x;
    if (i < n_dst) g_count[i] = 0;
}

__global__ __launch_bounds__(256) void hist_kernel(const void* __restrict__ dst_idx, int E) {
    int i = blockIdx.x * blockDim.x + threadIdx.x;
    if (i < E) atomicAdd(&g_count[load_idx(dst_idx, i)], 1);
}

// ---------------- parallel exclusive scan (3 kernels) ----------------
__global__ __launch_bounds__(256) void scan_bsum_kernel(int n_dst) {
    int t = threadIdx.x;
    int base = blockIdx.x * 1024 + t * 4;
    int v = 0;
    #pragma unroll
    for (int j = 0; j < 4; j++) {
        int i = base + j;
        if (i < n_dst) v += g_count[i];
    }
    #pragma unroll
    for (int off = 16; off; off >>= 1) v += __shfl_xor_sync(0xFFFFFFFFu, v, off);
    __shared__ int ws[8];
    if ((t & 31) == 0) ws[t >> 5] = v;
    __syncthreads();
    if (t < 8) {
        int u = ws[t];
        #pragma unroll
        for (int off = 4; off; off >>= 1) u += __shfl_xor_sync(0xFFu, u, off);
        if (t == 0) g_bsum[blockIdx.x] = u;
    }
}

__global__ __launch_bounds__(128) void scan_top_kernel(int nblocks) {
    __shared__ int s[128];
    int t = threadIdx.x;
    s[t] = (t < nblocks) ? g_bsum[t] : 0;
    __syncthreads();
    for (int off = 1; off < 128; off <<= 1) {
        int v = (t >= off) ? s[t - off] : 0;
        __syncthreads();
        s[t] += v;
        __syncthreads();
    }
    int excl = (t == 0) ? 0 : s[t - 1];
    if (t < nblocks) g_bsum[t] = excl;
}

__global__ __launch_bounds__(256) void scan_apply_kernel(int n_dst, int E) {
    __shared__ int ws[8];
    int t = threadIdx.x;
    int lane = t & 31, wid = t >> 5;
    int base = blockIdx.x * 1024 + t * 4;
    int c[4];
    int s_local = 0;
    #pragma unroll
    for (int j = 0; j < 4; j++) {
        int i = base + j;
        c[j] = (i < n_dst) ? g_count[i] : 0;
        s_local += c[j];
    }
    int v = s_local;
    #pragma unroll
    for (int off = 1; off < 32; off <<= 1) {
        int u = __shfl_up_sync(0xFFFFFFFFu, v, off);
        if (lane >= off) v += u;
    }
    if (lane == 31) ws[wid] = v;
    __syncthreads();
    if (t < 8) {
        int u = ws[t];
        #pragma unroll
        for (int off = 1; off < 8; off <<= 1) {
            int x = __shfl_up_sync(0xFFu, u, off);
            if (t >= off) u += x;
        }
        ws[t] = u;
    }
    __syncthreads();
    int run = v - s_local + (wid ? ws[wid - 1] : 0) + g_bsum[blockIdx.x];
    #pragma unroll
    for (int j = 0; j < 4; j++) {
        int i = base + j;
        if (i < n_dst) {
            g_start[i]  = run;
            g_cursor[i] = run;
            run += c[j];
        }
    }
    if (blockIdx.x == 0 && t == 0) g_start[n_dst] = E;
}

__global__ __launch_bounds__(256) void permute_kernel(
    const void* __restrict__ src_idx, const void* __restrict__ dst_idx, int E)
{
    int i = blockIdx.x * blockDim.x + threadIdx.x;
    if (i < E) {
        int s = load_idx(src_idx, i);
        int d = load_idx(dst_idx, i);
        int pos = atomicAdd(&g_cursor[d], 1);
        g_perm_src[pos] = s;
    }
}

// ---------------- projection GEMM (FFMA2): handles Q+K merged or V alone ----------------
#define XT_STRIDE 66
#define WT_STRIDE 132
#define PROJ_SMEM ((128 * XT_STRIDE + 128 * WT_STRIDE) * 4)

// mode 0: blocks [0,blocks_q) -> Q from dst_feat, [blocks_q,..) -> K from src_feat
// mode 1: all blocks -> V (fp16 out) from src_feat
__global__ __launch_bounds__(256) void proj_kernel(
    const float* __restrict__ dst_feat, const float* __restrict__ src_feat,
    const float* __restrict__ W0, const float* __restrict__ B0,
    const float* __restrict__ W1, const float* __restrict__ B1,
    int n_dst, int n_src, int blocks_q, int v_mode)
{
    extern __shared__ float sm[];
    float* Xt = sm;                        // [128 k][66]
    float* Wt = sm + 128 * XT_STRIDE;      // [128 k][132]

    const int tid = threadIdx.x;
    const int bid = blockIdx.x;

    const float *X, *W, *B;
    float* Y = nullptr;
    int N, row0;
    bool v_half;
    if (v_mode) {
        X = src_feat; W = W0; B = B0; N = n_src; row0 = bid * 64; v_half = true;
    } else if (bid < blocks_q) {
        X = dst_feat; W = W0; B = B0; Y = g_Q; N = n_dst; row0 = bid * 64; v_half = false;
    } else {
        X = src_feat; W = W1; B = B1; Y = g_K; N = n_src; row0 = (bid - blocks_q) * 64; v_half = false;
    }

    #pragma unroll 4
    for (int idx = tid; idx < 128 * 128; idx += 256) {
        int o = idx >> 7, k = idx & 127;
        Wt[k * WT_STRIDE + o] = W[idx];
    }
    #pragma unroll
    for (int idx = tid; idx < 64 * 32; idx += 256) {
        int r = idx >> 5, c4 = idx & 31;
        int row = row0 + r;
        float4 v = (row < N) ? ((const float4*)X)[(size_t)row * 32 + c4]
                             : make_float4(0.f, 0.f, 0.f, 0.f);
        Xt[(c4 * 4 + 0) * XT_STRIDE + r] = v.x;
        Xt[(c4 * 4 + 1) * XT_STRIDE + r] = v.y;
        Xt[(c4 * 4 + 2) * XT_STRIDE + r] = v.z;
        Xt[(c4 * 4 + 3) * XT_STRIDE + r] = v.w;
    }
    __syncthreads();

    const int tcol = tid & 31;
    const int trow = tid >> 5;

    unsigned long long acc[4][4];
    #pragma unroll
    for (int p = 0; p < 4; p++)
        #pragma unroll
        for (int j = 0; j < 4; j++) acc[p][j] = 0ULL;

    #pragma unroll 4
    for (int k = 0; k < 128; k++) {
        float4 w = *(const float4*)&Wt[k * WT_STRIDE + tcol * 4];
        unsigned long long wp0 = pack2(w.x), wp1 = pack2(w.y),
                           wp2 = pack2(w.z), wp3 = pack2(w.w);
        const unsigned long long* xrow =
            (const unsigned long long*)&Xt[k * XT_STRIDE + trow * 8];
        #pragma unroll
        for (int p = 0; p < 4; p++) {
            unsigned long long xp = xrow[p];
            fma2(acc[p][0], xp, wp0);
            fma2(acc[p][1], xp, wp1);
            fma2(acc[p][2], xp, wp2);
            fma2(acc[p][3], xp, wp3);
        }
    }

    float4 bias = *(const float4*)&B[tcol * 4];
    #pragma unroll
    for (int p = 0; p < 4; p++) {
        float2 a0 = *(float2*)&acc[p][0];
        float2 a1 = *(float2*)&acc[p][1];
        float2 a2 = *(float2*)&acc[p][2];
        float2 a3 = *(float2*)&acc[p][3];
        int row_e = row0 + trow * 8 + 2 * p;
        float4 oe = make_float4(a0.x + bias.x, a1.x + bias.y, a2.x + bias.z, a3.x + bias.w);
        float4 oo = make_float4(a0.y + bias.x, a1.y + bias.y, a2.y + bias.z, a3.y + bias.w);
        if (v_half) {
            if (row_e < N) {
                __half2 h0 = __floats2half2_rn(oe.x, oe.y);
                __half2 h1 = __floats2half2_rn(oe.z, oe.w);
                uint2 u; u.x = *(uint32_t*)&h0; u.y = *(uint32_t*)&h1;
                ((uint2*)(g_Vh + (size_t)row_e * 128))[tcol] = u;
            }
            if (row_e + 1 < N) {
                __half2 h0 = __floats2half2_rn(oo.x, oo.y);
                __half2 h1 = __floats2half2_rn(oo.z, oo.w);
                uint2 u; u.x = *(uint32_t*)&h0; u.y = *(uint32_t*)&h1;
                ((uint2*)(g_Vh + (size_t)(row_e + 1) * 128))[tcol] = u;
            }
        } else {
            if (row_e < N)     ((float4*)Y)[(size_t)row_e * 32 + tcol] = oe;
            if (row_e + 1 < N) ((float4*)Y)[(size_t)(row_e + 1) * 32 + tcol] = oo;
        }
    }
}

// ---------------- phase 1: scores + exact segment max (needs Q, K, sort) ----------------
__global__ __launch_bounds__(256) void score_kernel(int n_dst)
{
    int w = (blockIdx.x * blockDim.x + threadIdx.x) >> 5;
    if (w >= n_dst) return;
    int lane = threadIdx.x & 31;

    int start = g_start[w];
    int end   = g_start[w + 1];

    float4 q = ((const float4*)(g_Q + (size_t)w * D))[lane];

    float m = -CUDART_INF_F;
    for (int p = start; p < end; ++p) {
        int s = __ldg(&g_perm_src[p]);
        float4 k = ((const float4*)(g_K + (size_t)s * D))[lane];
        float dot = q.x * k.x + q.y * k.y + q.z * k.z + q.w * k.w;
        #pragma unroll
        for (int off = 16; off > 0; off >>= 1)
            dot += __shfl_xor_sync(0xFFFFFFFFu, dot, off);
        float sc = dot * INV_SCALE;
        m = fmaxf(m, sc);
        if (lane == 0) g_score[p] = sc;
    }
    if (lane == 0) g_m[w] = m;
}

// ---------------- phase 2: exact softmax + weighted V accumulation ----------------
__global__ __launch_bounds__(256) void accum_kernel(float* __restrict__ out, int n_dst)
{
    int w = (blockIdx.x * blockDim.x + threadIdx.x) >> 5;
    if (w >= n_dst) return;
    int lane = threadIdx.x & 31;

    int start = g_start[w];
    int end   = g_start[w + 1];
    float m = g_m[w];

    float denom = 0.0f;
    float4 acc = make_float4(0.f, 0.f, 0.f, 0.f);

    for (int p = start; p < end; ++p) {
        int s = __ldg(&g_perm_src[p]);
        float wgt = __expf(__ldg(&g_score[p]) - m);
        uint2 vv = ((const uint2*)(g_Vh + (size_t)s * D))[lane];
        float2 v01 = __half22float2(*(__half2*)&vv.x);
        float2 v23 = __half22float2(*(__half2*)&vv.y);
        denom += wgt;
        acc.x += wgt * v01.x;
        acc.y += wgt * v01.y;
        acc.z += wgt * v23.x;
        acc.w += wgt * v23.y;
    }

    float inv = (denom > 0.0f) ? (1.0f / denom) : 0.0f;
    float4 r = make_float4(acc.x * inv, acc.y * inv, acc.z * inv, acc.w * inv);
    ((float4*)(out + (size_t)w * D))[lane] = r;
}

// ---------------- launch: two streams, score overlaps projV ----------------
extern "C" void kernel_launch(void* const* d_in, const int* in_sizes, int n_in,
                              void* d_out, int out_size)
{
    const float* src_feat = (const float*)d_in[0];
    const float* dst_feat = (const float*)d_in[1];
    const void*  src_idx  = d_in[2];
    const void*  dst_idx  = d_in[3];
    const float* Wq = (const float*)d_in[4];
    const float* bq = (const float*)d_in[5];
    const float* Wk = (const float*)d_in[6];
    const float* bk = (const float*)d_in[7];
    const float* Wv = (const float*)d_in[8];
    const float* bv = (const float*)d_in[9];
    float* out = (float*)d_out;

    int n_src = in_sizes[0] / D;
    int n_dst = in_sizes[1] / D;
    int E     = in_sizes[2];

    static cudaStream_t s2 = nullptr;
    static cudaEvent_t evFork = nullptr, evQK = nullptr, evScore = nullptr;
    static int attr_set = 0;
    if (!attr_set) {
        cudaFuncSetAttribute(proj_kernel, cudaFuncAttributeMaxDynamicSharedMemorySize, PROJ_SMEM);
        cudaStreamCreateWithFlags(&s2, cudaStreamNonBlocking);
        cudaEventCreateWithFlags(&evFork, cudaEventDisableTiming);
        cudaEventCreateWithFlags(&evQK, cudaEventDisableTiming);
        cudaEventCreateWithFlags(&evScore, cudaEventDisableTiming);
        attr_set = 1;
    }

    int blocks_q = (n_dst + 63) / 64;
    int blocks_k = (n_src + 63) / 64;
    int blocks_v = (n_src + 63) / 64;

    // Fork: stream B handles the index/sort chain.
    cudaEventRecord(evFork, 0);
    cudaStreamWaitEvent(s2, evFork, 0);

    detect_idx_kernel<<<1, 64, 0, s2>>>(src_idx, dst_idx, n_src, n_dst, E);
    zero_counts_kernel<<<(n_dst + 255) / 256, 256, 0, s2>>>(n_dst);
    hist_kernel<<<(E + 255) / 256, 256, 0, s2>>>(dst_idx, E);
    int scan_blocks = (n_dst + 1023) / 1024;
    scan_bsum_kernel<<<scan_blocks, 256, 0, s2>>>(n_dst);
    scan_top_kernel<<<1, 128, 0, s2>>>(scan_blocks);
    scan_apply_kernel<<<scan_blocks, 256, 0, s2>>>(n_dst, E);
    permute_kernel<<<(E + 255) / 256, 256, 0, s2>>>(src_idx, dst_idx, E);

    // Stream A: project Q and K first (merged), then V.
    proj_kernel<<<blocks_q + blocks_k, 256, PROJ_SMEM>>>(
        dst_feat, src_feat, Wq, bq, Wk, bk, n_dst, n_src, blocks_q, 0);
    cudaEventRecord(evQK, 0);

    proj_kernel<<<blocks_v, 256, PROJ_SMEM>>>(
        dst_feat, src_feat, Wv, bv, nullptr, nullptr, n_dst, n_src, 0, 1);

    // Stream B: scores overlap with projV (needs Q, K, and the sort).
    cudaStreamWaitEvent(s2, evQK, 0);
    score_kernel<<<(n_dst + 7) / 8, 256, 0, s2>>>(n_dst);
    cudaEventRecord(evScore, s2);

    // Join: accumulation needs V and the scores.
    cudaStreamWaitEvent(0, evScore, 0);
    accum_kernel<<<(n_dst + 7) / 8, 256>>>(out, n_dst);
}